// round 1
// baseline (speedup 1.0000x reference)
#include <cuda_runtime.h>

#define NP 50000
#define NA 30000
#define NS 60
#define D  128

// relation order: 0 wb(P->A), 1 w(A->P), 2 c(P->P), 3 cd(P->P), 4 ia(P->S), 5 h(S->P)
#define E_TOT    1500000
#define NDST_TOT 230060   // 30000+50000+50000+50000+60+50000
#define NOFF_TOT 230066

// deg bases:  wb 0, w 30000, c 80000, cd 130000, ia 180000, h 180060
// off bases:  wb 0, w 30001, c 80002, cd 130003, ia 180004, h 180065
// srt bases:  wb 0, w 200000, c 400000, cd 900000, ia 1400000, h 1450000
// Wh  bases (floats): w 0, c NA*D, cd (NA+NP)*D, h (NA+2*NP)*D
// agg bases (floats): wb 0, ia NA*D

__device__ int   g_deg[NDST_TOT];
__device__ int   g_off[NOFF_TOT];
__device__ int   g_cur[NDST_TOT];
__device__ int   g_srt[E_TOT];
__device__ float g_Wh[(NA + NP + NP + NS) * D];
__device__ float g_agg[(NA + NS) * D];

// ---------------------------------------------------------------------------
__global__ void zero_kernel() {
    int i = blockIdx.x * blockDim.x + threadIdx.x;
    if (i < NDST_TOT) g_deg[i] = 0;
}

// ---------------------------------------------------------------------------
__global__ void count_kernel(const int* __restrict__ d0, const int* __restrict__ d1,
                             const int* __restrict__ d2, const int* __restrict__ d3,
                             const int* __restrict__ d4, const int* __restrict__ d5) {
    int g = blockIdx.x * blockDim.x + threadIdx.x;
    if (g >= E_TOT) return;
    const int* dp; int e, db;
    if      (g <  200000) { dp = d0; e = g;           db = 0;      }
    else if (g <  400000) { dp = d1; e = g -  200000; db = 30000;  }
    else if (g <  900000) { dp = d2; e = g -  400000; db = 80000;  }
    else if (g < 1400000) { dp = d3; e = g -  900000; db = 130000; }
    else if (g < 1450000) { dp = d4; e = g - 1400000; db = 180000; }
    else                  { dp = d5; e = g - 1450000; db = 180060; }
    atomicAdd(&g_deg[db + dp[e]], 1);
}

// ---------------------------------------------------------------------------
// One block per relation: exclusive scan of degrees -> offsets (+cursor copy).
__global__ void scan_kernel() {
    int r = blockIdx.x;
    int n, db, ob;
    switch (r) {
        case 0: n = 30000; db = 0;      ob = 0;      break;
        case 1: n = 50000; db = 30000;  ob = 30001;  break;
        case 2: n = 50000; db = 80000;  ob = 80002;  break;
        case 3: n = 50000; db = 130000; ob = 130003; break;
        case 4: n = 60;    db = 180000; ob = 180004; break;
        default:n = 50000; db = 180060; ob = 180065; break;
    }
    __shared__ int warpsum[32];
    int tid = threadIdx.x;           // 1024 threads
    int base = 0;
    for (int start = 0; start < n; start += 1024) {
        __syncthreads();             // protect warpsum from previous iteration
        int i = start + tid;
        int v = (i < n) ? g_deg[db + i] : 0;
        int x = v;
        #pragma unroll
        for (int o = 1; o < 32; o <<= 1) {
            int t = __shfl_up_sync(0xffffffffu, x, o);
            if ((tid & 31) >= o) x += t;
        }
        if ((tid & 31) == 31) warpsum[tid >> 5] = x;
        __syncthreads();
        if (tid < 32) {
            int y = warpsum[tid];
            #pragma unroll
            for (int o = 1; o < 32; o <<= 1) {
                int t = __shfl_up_sync(0xffffffffu, y, o);
                if (tid >= o) y += t;
            }
            warpsum[tid] = y;
        }
        __syncthreads();
        int wb = (tid >= 32) ? warpsum[(tid >> 5) - 1] : 0;
        int excl = base + wb + x - v;
        if (i < n) { g_off[ob + i] = excl; g_cur[db + i] = excl; }
        base += warpsum[31];
    }
    if (tid == 0) g_off[ob + n] = base;
}

// ---------------------------------------------------------------------------
__global__ void fill_kernel(const int* __restrict__ s0, const int* __restrict__ d0,
                            const int* __restrict__ s1, const int* __restrict__ d1,
                            const int* __restrict__ s2, const int* __restrict__ d2,
                            const int* __restrict__ s3, const int* __restrict__ d3,
                            const int* __restrict__ s4, const int* __restrict__ d4,
                            const int* __restrict__ s5, const int* __restrict__ d5) {
    int g = blockIdx.x * blockDim.x + threadIdx.x;
    if (g >= E_TOT) return;
    const int *sp, *dp; int e, db, sb;
    if      (g <  200000) { sp = s0; dp = d0; e = g;           db = 0;      sb = 0;       }
    else if (g <  400000) { sp = s1; dp = d1; e = g -  200000; db = 30000;  sb = 200000;  }
    else if (g <  900000) { sp = s2; dp = d2; e = g -  400000; db = 80000;  sb = 400000;  }
    else if (g < 1400000) { sp = s3; dp = d3; e = g -  900000; db = 130000; sb = 900000;  }
    else if (g < 1450000) { sp = s4; dp = d4; e = g - 1400000; db = 180000; sb = 1400000; }
    else                  { sp = s5; dp = d5; e = g - 1450000; db = 180060; sb = 1450000; }
    int pos = atomicAdd(&g_cur[db + dp[e]], 1);
    g_srt[sb + pos] = sp[e];
}

// ---------------------------------------------------------------------------
// C[M,128] = A[M,128] @ W[128,128] + b  (optionally bias-masked by degree>0)
// Block tile: 128 rows x 64 cols, 256 threads, 8x4 microtile. 48KB static smem.
__global__ void gemm_k(const float* __restrict__ Aext, int aggOff,
                       const float* __restrict__ W, const float* __restrict__ bias,
                       float* __restrict__ Cext, int whOff,
                       int M, int maskBase) {
    __shared__ float Ws[128 * 64];
    __shared__ float As[128 * 32];
    const float* A = (aggOff >= 0) ? (g_agg + aggOff) : Aext;
    float* C = (whOff >= 0) ? (g_Wh + whOff) : Cext;

    int tid = threadIdx.x;
    int n0 = blockIdx.y * 64;
    int m0 = blockIdx.x * 128;

    for (int i = tid; i < 2048; i += 256) {
        int row = i >> 4, c4 = (i & 15) * 4;
        *(float4*)&Ws[row * 64 + c4] = *(const float4*)&W[row * 128 + n0 + c4];
    }

    int r0 = (tid >> 4) * 8;
    int j0 = (tid & 15) * 4;
    float4 acc[8];
    #pragma unroll
    for (int i = 0; i < 8; i++) acc[i] = make_float4(0.f, 0.f, 0.f, 0.f);

    for (int kc = 0; kc < 128; kc += 32) {
        __syncthreads();
        for (int i = tid; i < 1024; i += 256) {
            int row = i >> 3, c4 = (i & 7) * 4;
            int m = m0 + row;
            float4 v = make_float4(0.f, 0.f, 0.f, 0.f);
            if (m < M) v = *(const float4*)&A[m * 128 + kc + c4];
            *(float4*)&As[row * 32 + c4] = v;
        }
        __syncthreads();
        #pragma unroll
        for (int kk = 0; kk < 32; kk++) {
            float4 bv = *(float4*)&Ws[(kc + kk) * 64 + j0];
            #pragma unroll
            for (int i = 0; i < 8; i++) {
                float a = As[(r0 + i) * 32 + kk];
                acc[i].x += a * bv.x; acc[i].y += a * bv.y;
                acc[i].z += a * bv.z; acc[i].w += a * bv.w;
            }
        }
    }

    float4 bv = *(const float4*)&bias[n0 + j0];
    #pragma unroll
    for (int i = 0; i < 8; i++) {
        int m = m0 + r0 + i;
        if (m >= M) continue;
        float4 o;
        if (maskBase >= 0) {
            int dg = g_off[maskBase + m + 1] - g_off[maskBase + m];
            if (dg == 0) o = make_float4(0.f, 0.f, 0.f, 0.f);
            else o = make_float4(acc[i].x + bv.x, acc[i].y + bv.y,
                                 acc[i].z + bv.z, acc[i].w + bv.w);
        } else {
            o = make_float4(acc[i].x + bv.x, acc[i].y + bv.y,
                            acc[i].z + bv.z, acc[i].w + bv.w);
        }
        *(float4*)&C[m * 128 + n0 + j0] = o;
    }
}

// ---------------------------------------------------------------------------
// h_paper: one warp per paper dst, fused over 4 relations (w, c, cd, h).
__global__ void agg_paper(float* __restrict__ out) {
    int w = (blockIdx.x * blockDim.x + threadIdx.x) >> 5;
    if (w >= NP) return;
    int lane = threadIdx.x & 31;
    float4 acc = make_float4(0.f, 0.f, 0.f, 0.f);

    const int offB[4] = {30001, 80002, 130003, 180065};
    const int srtB[4] = {200000, 400000, 900000, 1450000};
    const int whB[4]  = {0, NA * D, (NA + NP) * D, (NA + 2 * NP) * D};

    #pragma unroll
    for (int r = 0; r < 4; r++) {
        int s = g_off[offB[r] + w];
        int e = g_off[offB[r] + w + 1];
        int cnt = e - s;
        if (cnt > 0) {
            const float* whb = g_Wh + whB[r];
            float4 sum = make_float4(0.f, 0.f, 0.f, 0.f);
            int idx = s;
            for (; idx + 1 < e; idx += 2) {
                int a0 = g_srt[srtB[r] + idx];
                int a1 = g_srt[srtB[r] + idx + 1];
                float4 v0 = *(const float4*)&whb[a0 * D + lane * 4];
                float4 v1 = *(const float4*)&whb[a1 * D + lane * 4];
                sum.x += v0.x + v1.x; sum.y += v0.y + v1.y;
                sum.z += v0.z + v1.z; sum.w += v0.w + v1.w;
            }
            if (idx < e) {
                int a0 = g_srt[srtB[r] + idx];
                float4 v0 = *(const float4*)&whb[a0 * D + lane * 4];
                sum.x += v0.x; sum.y += v0.y; sum.z += v0.z; sum.w += v0.w;
            }
            float inv = 1.f / (float)cnt;
            acc.x += sum.x * inv; acc.y += sum.y * inv;
            acc.z += sum.z * inv; acc.w += sum.w * inv;
        }
    }
    *(float4*)&out[w * D + lane * 4] = acc;
}

// ---------------------------------------------------------------------------
// mean(x_paper) onto authors (relation wb): warp per author -> g_agg[0..]
__global__ void agg_author(const float* __restrict__ xp) {
    int w = (blockIdx.x * blockDim.x + threadIdx.x) >> 5;
    if (w >= NA) return;
    int lane = threadIdx.x & 31;
    int s = g_off[w];
    int e = g_off[w + 1];
    int cnt = e - s;
    float4 sum = make_float4(0.f, 0.f, 0.f, 0.f);
    int idx = s;
    for (; idx + 1 < e; idx += 2) {
        int a0 = g_srt[idx];
        int a1 = g_srt[idx + 1];
        float4 v0 = *(const float4*)&xp[a0 * D + lane * 4];
        float4 v1 = *(const float4*)&xp[a1 * D + lane * 4];
        sum.x += v0.x + v1.x; sum.y += v0.y + v1.y;
        sum.z += v0.z + v1.z; sum.w += v0.w + v1.w;
    }
    if (idx < e) {
        int a0 = g_srt[idx];
        float4 v0 = *(const float4*)&xp[a0 * D + lane * 4];
        sum.x += v0.x; sum.y += v0.y; sum.z += v0.z; sum.w += v0.w;
    }
    float inv = (cnt > 0) ? 1.f / (float)cnt : 0.f;
    float4 o = make_float4(sum.x * inv, sum.y * inv, sum.z * inv, sum.w * inv);
    *(float4*)&g_agg[w * D + lane * 4] = o;
}

// ---------------------------------------------------------------------------
// mean(x_paper) onto subjects (relation ia): one 128-thread block per subject.
__global__ void agg_subject(const float* __restrict__ xp) {
    int dno = blockIdx.x;          // 0..59
    int j = threadIdx.x;           // 0..127
    int s = g_off[180004 + dno];
    int e = g_off[180004 + dno + 1];
    int cnt = e - s;
    float sum = 0.f;
    int idx = s;
    for (; idx + 3 < e; idx += 4) {
        int a = g_srt[1400000 + idx];
        int b = g_srt[1400000 + idx + 1];
        int c = g_srt[1400000 + idx + 2];
        int d = g_srt[1400000 + idx + 3];
        sum += xp[a * D + j] + xp[b * D + j] + xp[c * D + j] + xp[d * D + j];
    }
    for (; idx < e; idx++) sum += xp[g_srt[1400000 + idx] * D + j];
    g_agg[(NA + dno) * D + j] = (cnt > 0) ? sum / (float)cnt : 0.f;
}

// ---------------------------------------------------------------------------
extern "C" void kernel_launch(void* const* d_in, const int* in_sizes, int n_in,
                              void* d_out, int out_size) {
    const float* x_paper   = (const float*)d_in[0];
    const float* x_author  = (const float*)d_in[1];
    const float* x_subject = (const float*)d_in[2];
    const float* W_wb = (const float*)d_in[3];  const float* b_wb = (const float*)d_in[4];
    const float* W_w  = (const float*)d_in[5];  const float* b_w  = (const float*)d_in[6];
    const float* W_c  = (const float*)d_in[7];  const float* b_c  = (const float*)d_in[8];
    const float* W_cd = (const float*)d_in[9];  const float* b_cd = (const float*)d_in[10];
    const float* W_ia = (const float*)d_in[11]; const float* b_ia = (const float*)d_in[12];
    const float* W_h  = (const float*)d_in[13]; const float* b_h  = (const float*)d_in[14];
    const int* src_wb = (const int*)d_in[15];   const int* dst_wb = (const int*)d_in[16];
    const int* src_w  = (const int*)d_in[17];   const int* dst_w  = (const int*)d_in[18];
    const int* src_c  = (const int*)d_in[19];   const int* dst_c  = (const int*)d_in[20];
    const int* src_cd = (const int*)d_in[21];   const int* dst_cd = (const int*)d_in[22];
    const int* src_ia = (const int*)d_in[23];   const int* dst_ia = (const int*)d_in[24];
    const int* src_h  = (const int*)d_in[25];   const int* dst_h  = (const int*)d_in[26];

    float* out         = (float*)d_out;
    float* out_paper   = out;
    float* out_author  = out + NP * D;
    float* out_subject = out + (NP + NA) * D;

    // CSR build
    zero_kernel<<<(NDST_TOT + 255) / 256, 256>>>();
    count_kernel<<<(E_TOT + 255) / 256, 256>>>(dst_wb, dst_w, dst_c, dst_cd, dst_ia, dst_h);
    scan_kernel<<<6, 1024>>>();
    fill_kernel<<<(E_TOT + 255) / 256, 256>>>(src_wb, dst_wb, src_w, dst_w,
                                              src_c, dst_c, src_cd, dst_cd,
                                              src_ia, dst_ia, src_h, dst_h);

    // Project-first GEMMs -> g_Wh
    gemm_k<<<dim3((NA + 127) / 128, 2), 256>>>(x_author,  -1, W_w,  b_w,  nullptr, 0,                NA, -1);
    gemm_k<<<dim3((NP + 127) / 128, 2), 256>>>(x_paper,   -1, W_c,  b_c,  nullptr, NA * D,           NP, -1);
    gemm_k<<<dim3((NP + 127) / 128, 2), 256>>>(x_paper,   -1, W_cd, b_cd, nullptr, (NA + NP) * D,    NP, -1);
    gemm_k<<<dim3((NS + 127) / 128, 2), 256>>>(x_subject, -1, W_h,  b_h,  nullptr, (NA + 2 * NP) * D, NS, -1);

    // Aggregate-first relations: mean raw features, then project
    agg_author<<<(NA * 32 + 255) / 256, 256>>>(x_paper);
    agg_subject<<<NS, 128>>>(x_paper);
    gemm_k<<<dim3((NA + 127) / 128, 2), 256>>>(nullptr, 0,      W_wb, b_wb, out_author,  -1, NA, 0);
    gemm_k<<<dim3((NS + 127) / 128, 2), 256>>>(nullptr, NA * D, W_ia, b_ia, out_subject, -1, NS, 180004);

    // Fused 4-relation mean-gather into h_paper
    agg_paper<<<(NP * 32 + 255) / 256, 256>>>(out_paper);
}

// round 2
// speedup vs baseline: 1.4219x; 1.4219x over previous
#include <cuda_runtime.h>

#define NP 50000
#define NA 30000
#define NS 60
#define D  128

// relation order: 0 wb(P->A), 1 w(A->P), 2 c(P->P), 3 cd(P->P), 4 ia(P->S), 5 h(S->P)
#define E_TOT    1500000
#define NDST_TOT 230060   // 30000+50000+50000+50000+60+50000
#define NOFF_TOT 230066

// deg bases:  wb 0, w 30000, c 80000, cd 130000, ia 180000, h 180060
// off bases:  wb 0, w 30001, c 80002, cd 130003, ia 180004, h 180065
// srt bases:  wb 0, w 200000, c 400000, cd 900000, ia 1400000, h 1450000
// Wh  bases (floats): w 0, c NA*D, cd (NA+NP)*D, h (NA+2*NP)*D
// agg bases (floats): wb 0, ia NA*D

__device__ int   g_deg[NDST_TOT];
__device__ int   g_off[NOFF_TOT];
__device__ int   g_cur[NDST_TOT];
__device__ int   g_srt[E_TOT];
__device__ float g_Wh[(NA + NP + NP + NS) * D];
__device__ float g_agg[(NA + NS) * D];

// ---------------------------------------------------------------------------
__global__ void zero_kernel() {
    int i = blockIdx.x * blockDim.x + threadIdx.x;
    if (i < NDST_TOT) g_deg[i] = 0;
}

// ---------------------------------------------------------------------------
__global__ void count_kernel(const int* __restrict__ d0, const int* __restrict__ d1,
                             const int* __restrict__ d2, const int* __restrict__ d3,
                             const int* __restrict__ d4, const int* __restrict__ d5) {
    int g = blockIdx.x * blockDim.x + threadIdx.x;
    if (g >= E_TOT) return;
    const int* dp; int e, db;
    if      (g <  200000) { dp = d0; e = g;           db = 0;      }
    else if (g <  400000) { dp = d1; e = g -  200000; db = 30000;  }
    else if (g <  900000) { dp = d2; e = g -  400000; db = 80000;  }
    else if (g < 1400000) { dp = d3; e = g -  900000; db = 130000; }
    else if (g < 1450000) { dp = d4; e = g - 1400000; db = 180000; }
    else                  { dp = d5; e = g - 1450000; db = 180060; }
    atomicAdd(&g_deg[db + dp[e]], 1);
}

// ---------------------------------------------------------------------------
// One block per relation: exclusive scan of degrees -> offsets (+cursor copy).
__global__ void scan_kernel() {
    int r = blockIdx.x;
    int n, db, ob;
    switch (r) {
        case 0: n = 30000; db = 0;      ob = 0;      break;
        case 1: n = 50000; db = 30000;  ob = 30001;  break;
        case 2: n = 50000; db = 80000;  ob = 80002;  break;
        case 3: n = 50000; db = 130000; ob = 130003; break;
        case 4: n = 60;    db = 180000; ob = 180004; break;
        default:n = 50000; db = 180060; ob = 180065; break;
    }
    __shared__ int warpsum[32];
    int tid = threadIdx.x;           // 1024 threads
    int base = 0;
    for (int start = 0; start < n; start += 1024) {
        __syncthreads();             // protect warpsum from previous iteration
        int i = start + tid;
        int v = (i < n) ? g_deg[db + i] : 0;
        int x = v;
        #pragma unroll
        for (int o = 1; o < 32; o <<= 1) {
            int t = __shfl_up_sync(0xffffffffu, x, o);
            if ((tid & 31) >= o) x += t;
        }
        if ((tid & 31) == 31) warpsum[tid >> 5] = x;
        __syncthreads();
        if (tid < 32) {
            int y = warpsum[tid];
            #pragma unroll
            for (int o = 1; o < 32; o <<= 1) {
                int t = __shfl_up_sync(0xffffffffu, y, o);
                if (tid >= o) y += t;
            }
            warpsum[tid] = y;
        }
        __syncthreads();
        int wb = (tid >= 32) ? warpsum[(tid >> 5) - 1] : 0;
        int excl = base + wb + x - v;
        if (i < n) { g_off[ob + i] = excl; g_cur[db + i] = excl; }
        base += warpsum[31];
    }
    if (tid == 0) g_off[ob + n] = base;
}

// ---------------------------------------------------------------------------
__global__ void fill_kernel(const int* __restrict__ s0, const int* __restrict__ d0,
                            const int* __restrict__ s1, const int* __restrict__ d1,
                            const int* __restrict__ s2, const int* __restrict__ d2,
                            const int* __restrict__ s3, const int* __restrict__ d3,
                            const int* __restrict__ s4, const int* __restrict__ d4,
                            const int* __restrict__ s5, const int* __restrict__ d5) {
    int g = blockIdx.x * blockDim.x + threadIdx.x;
    if (g >= E_TOT) return;
    const int *sp, *dp; int e, db, sb;
    if      (g <  200000) { sp = s0; dp = d0; e = g;           db = 0;      sb = 0;       }
    else if (g <  400000) { sp = s1; dp = d1; e = g -  200000; db = 30000;  sb = 200000;  }
    else if (g <  900000) { sp = s2; dp = d2; e = g -  400000; db = 80000;  sb = 400000;  }
    else if (g < 1400000) { sp = s3; dp = d3; e = g -  900000; db = 130000; sb = 900000;  }
    else if (g < 1450000) { sp = s4; dp = d4; e = g - 1400000; db = 180000; sb = 1400000; }
    else                  { sp = s5; dp = d5; e = g - 1450000; db = 180060; sb = 1450000; }
    int pos = atomicAdd(&g_cur[db + dp[e]], 1);
    g_srt[sb + pos] = sp[e];
}

// ---------------------------------------------------------------------------
// C[M,128] = A[M,128] @ W[128,128] + b, f32x2 (FFMA2) inner loop.
// Block: 256 threads, tile 128(M) x 128(N). Microtile per thread:
// 8 rows (as 4 f32x2 row-pairs, A staged k-major in smem) x 8 cols.
// smem: Ws 128x128 (64KB) + At 32x130 (16.6KB) dynamic.
#define GEMM_SMEM ((16384 + 32 * 130) * 4)

__global__ void __launch_bounds__(256, 2)
gemm_k(const float* __restrict__ Aext, int aggOff,
       const float* __restrict__ W, const float* __restrict__ bias,
       float* __restrict__ Cext, int whOff, int M, int maskBase) {
    extern __shared__ float sm[];
    float* Ws = sm;            // [k][n] 128x128
    float* At = sm + 16384;    // [k][m] 32x130 (pad to kill bank conflicts)

    const float* A = (aggOff >= 0) ? (g_agg + aggOff) : Aext;
    float* C = (whOff >= 0) ? (g_Wh + whOff) : Cext;

    int tid = threadIdx.x;
    int m0 = blockIdx.x * 128;

    // Load full W tile (16384 floats = 4096 float4, 16 per thread)
    #pragma unroll
    for (int i = 0; i < 16; i++) {
        int idx = (tid + i * 256) * 4;
        *(float4*)&Ws[idx] = *(const float4*)&W[idx];
    }

    int r0 = (tid >> 4) * 8;        // row base (even)
    int j0 = (tid & 15) * 8;        // col base

    unsigned long long acc[4][8];
    #pragma unroll
    for (int p = 0; p < 4; p++)
        #pragma unroll
        for (int c = 0; c < 8; c++) acc[p][c] = 0ull;

    for (int kc = 0; kc < 128; kc += 32) {
        __syncthreads();
        // Stage A chunk transposed: At[k][m], 128 rows x 32 k each chunk
        #pragma unroll
        for (int i = 0; i < 4; i++) {
            int idx = tid + i * 256;          // 0..1023
            int row = idx >> 3;
            int k4  = (idx & 7) * 4;
            float4 v = make_float4(0.f, 0.f, 0.f, 0.f);
            if (m0 + row < M) v = *(const float4*)&A[(m0 + row) * 128 + kc + k4];
            At[(k4 + 0) * 130 + row] = v.x;
            At[(k4 + 1) * 130 + row] = v.y;
            At[(k4 + 2) * 130 + row] = v.z;
            At[(k4 + 3) * 130 + row] = v.w;
        }
        __syncthreads();

        const float* wsk = Ws + kc * 128 + j0;
        const float* atk = At + r0;
        #pragma unroll
        for (int kk = 0; kk < 32; kk++) {
            unsigned long long ap[4];
            #pragma unroll
            for (int p = 0; p < 4; p++)
                ap[p] = *(const unsigned long long*)&atk[kk * 130 + 2 * p];
            float4 b0 = *(const float4*)&wsk[kk * 128];
            float4 b1 = *(const float4*)&wsk[kk * 128 + 4];
            unsigned long long bd[8];
            asm("mov.b64 %0, {%1, %1};" : "=l"(bd[0]) : "f"(b0.x));
            asm("mov.b64 %0, {%1, %1};" : "=l"(bd[1]) : "f"(b0.y));
            asm("mov.b64 %0, {%1, %1};" : "=l"(bd[2]) : "f"(b0.z));
            asm("mov.b64 %0, {%1, %1};" : "=l"(bd[3]) : "f"(b0.w));
            asm("mov.b64 %0, {%1, %1};" : "=l"(bd[4]) : "f"(b1.x));
            asm("mov.b64 %0, {%1, %1};" : "=l"(bd[5]) : "f"(b1.y));
            asm("mov.b64 %0, {%1, %1};" : "=l"(bd[6]) : "f"(b1.z));
            asm("mov.b64 %0, {%1, %1};" : "=l"(bd[7]) : "f"(b1.w));
            #pragma unroll
            for (int p = 0; p < 4; p++)
                #pragma unroll
                for (int c = 0; c < 8; c++)
                    asm("fma.rn.f32x2 %0, %1, %2, %0;"
                        : "+l"(acc[p][c]) : "l"(ap[p]), "l"(bd[c]));
        }
    }

    // Epilogue: unpack, bias, optional degree-mask, store.
    float bias_r[8];
    #pragma unroll
    for (int c = 0; c < 8; c++) bias_r[c] = bias[j0 + c];

    #pragma unroll
    for (int p = 0; p < 4; p++) {
        #pragma unroll
        for (int h = 0; h < 2; h++) {
            int m = m0 + r0 + 2 * p + h;
            if (m >= M) continue;
            float o[8];
            #pragma unroll
            for (int c = 0; c < 8; c++) {
                unsigned long long v = acc[p][c];
                unsigned u = h ? (unsigned)(v >> 32) : (unsigned)v;
                o[c] = __uint_as_float(u) + bias_r[c];
            }
            if (maskBase >= 0) {
                int dg = g_off[maskBase + m + 1] - g_off[maskBase + m];
                if (dg == 0)
                    #pragma unroll
                    for (int c = 0; c < 8; c++) o[c] = 0.f;
            }
            *(float4*)&C[m * 128 + j0]     = make_float4(o[0], o[1], o[2], o[3]);
            *(float4*)&C[m * 128 + j0 + 4] = make_float4(o[4], o[5], o[6], o[7]);
        }
    }
}

// ---------------------------------------------------------------------------
// h_paper: one warp per paper dst, fused over 4 relations (w, c, cd, h).
__global__ void agg_paper(float* __restrict__ out) {
    int w = (blockIdx.x * blockDim.x + threadIdx.x) >> 5;
    if (w >= NP) return;
    int lane = threadIdx.x & 31;
    float4 acc = make_float4(0.f, 0.f, 0.f, 0.f);

    const int offB[4] = {30001, 80002, 130003, 180065};
    const int srtB[4] = {200000, 400000, 900000, 1450000};
    const int whB[4]  = {0, NA * D, (NA + NP) * D, (NA + 2 * NP) * D};

    #pragma unroll
    for (int r = 0; r < 4; r++) {
        int s = g_off[offB[r] + w];
        int e = g_off[offB[r] + w + 1];
        int cnt = e - s;
        if (cnt > 0) {
            const float* whb = g_Wh + whB[r];
            float4 sum = make_float4(0.f, 0.f, 0.f, 0.f);
            int idx = s;
            for (; idx + 1 < e; idx += 2) {
                int a0 = g_srt[srtB[r] + idx];
                int a1 = g_srt[srtB[r] + idx + 1];
                float4 v0 = *(const float4*)&whb[a0 * D + lane * 4];
                float4 v1 = *(const float4*)&whb[a1 * D + lane * 4];
                sum.x += v0.x + v1.x; sum.y += v0.y + v1.y;
                sum.z += v0.z + v1.z; sum.w += v0.w + v1.w;
            }
            if (idx < e) {
                int a0 = g_srt[srtB[r] + idx];
                float4 v0 = *(const float4*)&whb[a0 * D + lane * 4];
                sum.x += v0.x; sum.y += v0.y; sum.z += v0.z; sum.w += v0.w;
            }
            float inv = 1.f / (float)cnt;
            acc.x += sum.x * inv; acc.y += sum.y * inv;
            acc.z += sum.z * inv; acc.w += sum.w * inv;
        }
    }
    *(float4*)&out[w * D + lane * 4] = acc;
}

// ---------------------------------------------------------------------------
// mean(x_paper) onto authors (relation wb): warp per author -> g_agg[0..]
__global__ void agg_author(const float* __restrict__ xp) {
    int w = (blockIdx.x * blockDim.x + threadIdx.x) >> 5;
    if (w >= NA) return;
    int lane = threadIdx.x & 31;
    int s = g_off[w];
    int e = g_off[w + 1];
    int cnt = e - s;
    float4 sum = make_float4(0.f, 0.f, 0.f, 0.f);
    int idx = s;
    for (; idx + 1 < e; idx += 2) {
        int a0 = g_srt[idx];
        int a1 = g_srt[idx + 1];
        float4 v0 = *(const float4*)&xp[a0 * D + lane * 4];
        float4 v1 = *(const float4*)&xp[a1 * D + lane * 4];
        sum.x += v0.x + v1.x; sum.y += v0.y + v1.y;
        sum.z += v0.z + v1.z; sum.w += v0.w + v1.w;
    }
    if (idx < e) {
        int a0 = g_srt[idx];
        float4 v0 = *(const float4*)&xp[a0 * D + lane * 4];
        sum.x += v0.x; sum.y += v0.y; sum.z += v0.z; sum.w += v0.w;
    }
    float inv = (cnt > 0) ? 1.f / (float)cnt : 0.f;
    float4 o = make_float4(sum.x * inv, sum.y * inv, sum.z * inv, sum.w * inv);
    *(float4*)&g_agg[w * D + lane * 4] = o;
}

// ---------------------------------------------------------------------------
// mean(x_paper) onto subjects (relation ia): one 128-thread block per subject.
__global__ void agg_subject(const float* __restrict__ xp) {
    int dno = blockIdx.x;          // 0..59
    int j = threadIdx.x;           // 0..127
    int s = g_off[180004 + dno];
    int e = g_off[180004 + dno + 1];
    int cnt = e - s;
    float sum = 0.f;
    int idx = s;
    for (; idx + 3 < e; idx += 4) {
        int a = g_srt[1400000 + idx];
        int b = g_srt[1400000 + idx + 1];
        int c = g_srt[1400000 + idx + 2];
        int d = g_srt[1400000 + idx + 3];
        sum += xp[a * D + j] + xp[b * D + j] + xp[c * D + j] + xp[d * D + j];
    }
    for (; idx < e; idx++) sum += xp[g_srt[1400000 + idx] * D + j];
    g_agg[(NA + dno) * D + j] = (cnt > 0) ? sum / (float)cnt : 0.f;
}

// ---------------------------------------------------------------------------
extern "C" void kernel_launch(void* const* d_in, const int* in_sizes, int n_in,
                              void* d_out, int out_size) {
    const float* x_paper   = (const float*)d_in[0];
    const float* x_author  = (const float*)d_in[1];
    const float* x_subject = (const float*)d_in[2];
    const float* W_wb = (const float*)d_in[3];  const float* b_wb = (const float*)d_in[4];
    const float* W_w  = (const float*)d_in[5];  const float* b_w  = (const float*)d_in[6];
    const float* W_c  = (const float*)d_in[7];  const float* b_c  = (const float*)d_in[8];
    const float* W_cd = (const float*)d_in[9];  const float* b_cd = (const float*)d_in[10];
    const float* W_ia = (const float*)d_in[11]; const float* b_ia = (const float*)d_in[12];
    const float* W_h  = (const float*)d_in[13]; const float* b_h  = (const float*)d_in[14];
    const int* src_wb = (const int*)d_in[15];   const int* dst_wb = (const int*)d_in[16];
    const int* src_w  = (const int*)d_in[17];   const int* dst_w  = (const int*)d_in[18];
    const int* src_c  = (const int*)d_in[19];   const int* dst_c  = (const int*)d_in[20];
    const int* src_cd = (const int*)d_in[21];   const int* dst_cd = (const int*)d_in[22];
    const int* src_ia = (const int*)d_in[23];   const int* dst_ia = (const int*)d_in[24];
    const int* src_h  = (const int*)d_in[25];   const int* dst_h  = (const int*)d_in[26];

    float* out         = (float*)d_out;
    float* out_paper   = out;
    float* out_author  = out + NP * D;
    float* out_subject = out + (NP + NA) * D;

    // One-time host-object setup (first call is the uncaptured correctness run)
    static cudaStream_t s1 = nullptr;
    static cudaEvent_t evA = nullptr, evB = nullptr, evC = nullptr, evD = nullptr;
    if (s1 == nullptr) {
        cudaStreamCreateWithFlags(&s1, cudaStreamNonBlocking);
        cudaEventCreateWithFlags(&evA, cudaEventDisableTiming);
        cudaEventCreateWithFlags(&evB, cudaEventDisableTiming);
        cudaEventCreateWithFlags(&evC, cudaEventDisableTiming);
        cudaEventCreateWithFlags(&evD, cudaEventDisableTiming);
        cudaFuncSetAttribute(gemm_k, cudaFuncAttributeMaxDynamicSharedMemorySize,
                             GEMM_SMEM);
    }

    // ---- fork: s1 runs the 4 project-first GEMMs ----
    cudaEventRecord(evA, 0);
    cudaStreamWaitEvent(s1, evA, 0);

    gemm_k<<<(NA + 127) / 128, 256, GEMM_SMEM, s1>>>(
        x_author,  -1, W_w,  b_w,  nullptr, 0,                 NA, -1);
    gemm_k<<<(NP + 127) / 128, 256, GEMM_SMEM, s1>>>(
        x_paper,   -1, W_c,  b_c,  nullptr, NA * D,            NP, -1);
    gemm_k<<<(NP + 127) / 128, 256, GEMM_SMEM, s1>>>(
        x_paper,   -1, W_cd, b_cd, nullptr, (NA + NP) * D,     NP, -1);
    gemm_k<<<(NS + 127) / 128, 256, GEMM_SMEM, s1>>>(
        x_subject, -1, W_h,  b_h,  nullptr, (NA + 2 * NP) * D, NS, -1);
    cudaEventRecord(evB, s1);

    // ---- s0 (capture stream): CSR build + raw-feature aggregations ----
    zero_kernel<<<(NDST_TOT + 255) / 256, 256>>>();
    count_kernel<<<(E_TOT + 255) / 256, 256>>>(dst_wb, dst_w, dst_c, dst_cd,
                                               dst_ia, dst_h);
    scan_kernel<<<6, 1024>>>();
    fill_kernel<<<(E_TOT + 255) / 256, 256>>>(src_wb, dst_wb, src_w, dst_w,
                                              src_c, dst_c, src_cd, dst_cd,
                                              src_ia, dst_ia, src_h, dst_h);
    agg_author<<<(NA * 32 + 255) / 256, 256>>>(x_paper);
    agg_subject<<<NS, 128>>>(x_paper);
    cudaEventRecord(evC, 0);

    // ---- s1: epilogue GEMMs (need g_agg + g_off) ----
    cudaStreamWaitEvent(s1, evC, 0);
    gemm_k<<<(NA + 127) / 128, 256, GEMM_SMEM, s1>>>(
        nullptr, 0,      W_wb, b_wb, out_author,  -1, NA, 0);
    gemm_k<<<(NS + 127) / 128, 256, GEMM_SMEM, s1>>>(
        nullptr, NA * D, W_ia, b_ia, out_subject, -1, NS, 180004);
    cudaEventRecord(evD, s1);

    // ---- s0: fused 4-relation gather (needs g_Wh from s1 + CSR) ----
    cudaStreamWaitEvent(0, evB, 0);
    agg_paper<<<(NP * 32 + 255) / 256, 256>>>(out_paper);

    // ---- join ----
    cudaStreamWaitEvent(0, evD, 0);
}

// round 3
// speedup vs baseline: 1.6113x; 1.1331x over previous
#include <cuda_runtime.h>

#define NP 50000
#define NA 30000
#define NS 60
#define D  128

// relation order: 0 wb(P->A), 1 w(A->P), 2 c(P->P), 3 cd(P->P), 4 ia(P->S), 5 h(S->P)
#define E_TOT    1500000
#define NDST_TOT 230060   // 30000+50000+50000+50000+60+50000
#define NOFF_TOT 230066

// deg bases:  wb 0, w 30000, c 80000, cd 130000, ia 180000, h 180060
// off bases:  wb 0, w 30001, c 80002, cd 130003, ia 180004, h 180065
// srt bases:  wb 0, w 200000, c 400000, cd 900000, ia 1400000, h 1450000
// Wh  bases (floats): w 0, c NA*D, cd (NA+NP)*D, h (NA+2*NP)*D
// agg bases (floats): wb 0, ia NA*D

__device__ int   g_deg[NDST_TOT];
__device__ int   g_off[NOFF_TOT];
__device__ int   g_cur[NDST_TOT];
__device__ int   g_srt[E_TOT];
__device__ float g_Wh[(NA + NP + NP + NS) * D];
__device__ float g_agg[(NA + NS) * D];

// ---------------------------------------------------------------------------
__global__ void zero_kernel() {
    int i = blockIdx.x * blockDim.x + threadIdx.x;
    if (i < NDST_TOT) g_deg[i] = 0;
}

// ---------------------------------------------------------------------------
// 4 edges per thread via int4 loads (MLP=4). 375000 threads.
__global__ void count_kernel(const int* __restrict__ d0, const int* __restrict__ d1,
                             const int* __restrict__ d2, const int* __restrict__ d3,
                             const int* __restrict__ d4, const int* __restrict__ d5) {
    int g = blockIdx.x * blockDim.x + threadIdx.x;
    if (g >= 375000) return;
    const int4* dp; int e, db;
    if      (g <  50000) { dp = (const int4*)d0; e = g;          db = 0;      }
    else if (g < 100000) { dp = (const int4*)d1; e = g -  50000; db = 30000;  }
    else if (g < 225000) { dp = (const int4*)d2; e = g - 100000; db = 80000;  }
    else if (g < 350000) { dp = (const int4*)d3; e = g - 225000; db = 130000; }
    else if (g < 362500) { dp = (const int4*)d4; e = g - 350000; db = 180000; }
    else                 { dp = (const int4*)d5; e = g - 362500; db = 180060; }
    int4 v = dp[e];
    atomicAdd(&g_deg[db + v.x], 1);
    atomicAdd(&g_deg[db + v.y], 1);
    atomicAdd(&g_deg[db + v.z], 1);
    atomicAdd(&g_deg[db + v.w], 1);
}

// ---------------------------------------------------------------------------
// One block per relation: exclusive scan of degrees -> offsets (+cursor copy).
__global__ void scan_kernel() {
    int r = blockIdx.x;
    int n, db, ob;
    switch (r) {
        case 0: n = 30000; db = 0;      ob = 0;      break;
        case 1: n = 50000; db = 30000;  ob = 30001;  break;
        case 2: n = 50000; db = 80000;  ob = 80002;  break;
        case 3: n = 50000; db = 130000; ob = 130003; break;
        case 4: n = 60;    db = 180000; ob = 180004; break;
        default:n = 50000; db = 180060; ob = 180065; break;
    }
    __shared__ int warpsum[32];
    int tid = threadIdx.x;           // 1024 threads
    int base = 0;
    for (int start = 0; start < n; start += 1024) {
        __syncthreads();
        int i = start + tid;
        int v = (i < n) ? g_deg[db + i] : 0;
        int x = v;
        #pragma unroll
        for (int o = 1; o < 32; o <<= 1) {
            int t = __shfl_up_sync(0xffffffffu, x, o);
            if ((tid & 31) >= o) x += t;
        }
        if ((tid & 31) == 31) warpsum[tid >> 5] = x;
        __syncthreads();
        if (tid < 32) {
            int y = warpsum[tid];
            #pragma unroll
            for (int o = 1; o < 32; o <<= 1) {
                int t = __shfl_up_sync(0xffffffffu, y, o);
                if (tid >= o) y += t;
            }
            warpsum[tid] = y;
        }
        __syncthreads();
        int wb = (tid >= 32) ? warpsum[(tid >> 5) - 1] : 0;
        int excl = base + wb + x - v;
        if (i < n) { g_off[ob + i] = excl; g_cur[db + i] = excl; }
        base += warpsum[31];
    }
    if (tid == 0) g_off[ob + n] = base;
}

// ---------------------------------------------------------------------------
// 4 edges per thread via int4 loads (MLP=4).
__global__ void fill_kernel(const int* __restrict__ s0, const int* __restrict__ d0,
                            const int* __restrict__ s1, const int* __restrict__ d1,
                            const int* __restrict__ s2, const int* __restrict__ d2,
                            const int* __restrict__ s3, const int* __restrict__ d3,
                            const int* __restrict__ s4, const int* __restrict__ d4,
                            const int* __restrict__ s5, const int* __restrict__ d5) {
    int g = blockIdx.x * blockDim.x + threadIdx.x;
    if (g >= 375000) return;
    const int4 *sp, *dp; int e, db, sb;
    if      (g <  50000) { sp = (const int4*)s0; dp = (const int4*)d0; e = g;          db = 0;      sb = 0;       }
    else if (g < 100000) { sp = (const int4*)s1; dp = (const int4*)d1; e = g -  50000; db = 30000;  sb = 200000;  }
    else if (g < 225000) { sp = (const int4*)s2; dp = (const int4*)d2; e = g - 100000; db = 80000;  sb = 400000;  }
    else if (g < 350000) { sp = (const int4*)s3; dp = (const int4*)d3; e = g - 225000; db = 130000; sb = 900000;  }
    else if (g < 362500) { sp = (const int4*)s4; dp = (const int4*)d4; e = g - 350000; db = 180000; sb = 1400000; }
    else                 { sp = (const int4*)s5; dp = (const int4*)d5; e = g - 362500; db = 180060; sb = 1450000; }
    int4 dv = dp[e];
    int4 sv = sp[e];
    int p0 = atomicAdd(&g_cur[db + dv.x], 1);
    int p1 = atomicAdd(&g_cur[db + dv.y], 1);
    int p2 = atomicAdd(&g_cur[db + dv.z], 1);
    int p3 = atomicAdd(&g_cur[db + dv.w], 1);
    g_srt[sb + p0] = sv.x;
    g_srt[sb + p1] = sv.y;
    g_srt[sb + p2] = sv.z;
    g_srt[sb + p3] = sv.w;
}

// ---------------------------------------------------------------------------
// Big GEMM: C[M,128] = A[M,128] @ W[128,128] + b, f32x2 (FFMA2) inner loop.
#define GEMM_SMEM ((16384 + 32 * 130) * 4)

__global__ void __launch_bounds__(256, 2)
gemm_k(const float* __restrict__ Aext, int aggOff,
       const float* __restrict__ W, const float* __restrict__ bias,
       float* __restrict__ Cext, int whOff, int M, int maskBase) {
    extern __shared__ float sm[];
    float* Ws = sm;            // [k][n] 128x128
    float* At = sm + 16384;    // [k][m] 32x130

    const float* A = (aggOff >= 0) ? (g_agg + aggOff) : Aext;
    float* C = (whOff >= 0) ? (g_Wh + whOff) : Cext;

    int tid = threadIdx.x;
    int m0 = blockIdx.x * 128;

    #pragma unroll
    for (int i = 0; i < 16; i++) {
        int idx = (tid + i * 256) * 4;
        *(float4*)&Ws[idx] = *(const float4*)&W[idx];
    }

    int r0 = (tid >> 4) * 8;
    int j0 = (tid & 15) * 8;

    unsigned long long acc[4][8];
    #pragma unroll
    for (int p = 0; p < 4; p++)
        #pragma unroll
        for (int c = 0; c < 8; c++) acc[p][c] = 0ull;

    for (int kc = 0; kc < 128; kc += 32) {
        __syncthreads();
        #pragma unroll
        for (int i = 0; i < 4; i++) {
            int idx = tid + i * 256;
            int row = idx >> 3;
            int k4  = (idx & 7) * 4;
            float4 v = make_float4(0.f, 0.f, 0.f, 0.f);
            if (m0 + row < M) v = *(const float4*)&A[(m0 + row) * 128 + kc + k4];
            At[(k4 + 0) * 130 + row] = v.x;
            At[(k4 + 1) * 130 + row] = v.y;
            At[(k4 + 2) * 130 + row] = v.z;
            At[(k4 + 3) * 130 + row] = v.w;
        }
        __syncthreads();

        const float* wsk = Ws + kc * 128 + j0;
        const float* atk = At + r0;
        #pragma unroll
        for (int kk = 0; kk < 32; kk++) {
            unsigned long long ap[4];
            #pragma unroll
            for (int p = 0; p < 4; p++)
                ap[p] = *(const unsigned long long*)&atk[kk * 130 + 2 * p];
            float4 b0 = *(const float4*)&wsk[kk * 128];
            float4 b1 = *(const float4*)&wsk[kk * 128 + 4];
            unsigned long long bd[8];
            asm("mov.b64 %0, {%1, %1};" : "=l"(bd[0]) : "f"(b0.x));
            asm("mov.b64 %0, {%1, %1};" : "=l"(bd[1]) : "f"(b0.y));
            asm("mov.b64 %0, {%1, %1};" : "=l"(bd[2]) : "f"(b0.z));
            asm("mov.b64 %0, {%1, %1};" : "=l"(bd[3]) : "f"(b0.w));
            asm("mov.b64 %0, {%1, %1};" : "=l"(bd[4]) : "f"(b1.x));
            asm("mov.b64 %0, {%1, %1};" : "=l"(bd[5]) : "f"(b1.y));
            asm("mov.b64 %0, {%1, %1};" : "=l"(bd[6]) : "f"(b1.z));
            asm("mov.b64 %0, {%1, %1};" : "=l"(bd[7]) : "f"(b1.w));
            #pragma unroll
            for (int p = 0; p < 4; p++)
                #pragma unroll
                for (int c = 0; c < 8; c++)
                    asm("fma.rn.f32x2 %0, %1, %2, %0;"
                        : "+l"(acc[p][c]) : "l"(ap[p]), "l"(bd[c]));
        }
    }

    float bias_r[8];
    #pragma unroll
    for (int c = 0; c < 8; c++) bias_r[c] = bias[j0 + c];

    #pragma unroll
    for (int p = 0; p < 4; p++) {
        #pragma unroll
        for (int h = 0; h < 2; h++) {
            int m = m0 + r0 + 2 * p + h;
            if (m >= M) continue;
            float o[8];
            #pragma unroll
            for (int c = 0; c < 8; c++) {
                unsigned long long v = acc[p][c];
                unsigned u = h ? (unsigned)(v >> 32) : (unsigned)v;
                o[c] = __uint_as_float(u) + bias_r[c];
            }
            if (maskBase >= 0) {
                int dg = g_off[maskBase + m + 1] - g_off[maskBase + m];
                if (dg == 0)
                    #pragma unroll
                    for (int c = 0; c < 8; c++) o[c] = 0.f;
            }
            *(float4*)&C[m * 128 + j0]     = make_float4(o[0], o[1], o[2], o[3]);
            *(float4*)&C[m * 128 + j0 + 4] = make_float4(o[4], o[5], o[6], o[7]);
        }
    }
}

// ---------------------------------------------------------------------------
// Small GEMM for M=60: grid.x = 8 col-tiles of 16 cols; A fully in smem.
__global__ void __launch_bounds__(256)
gemm_small(const float* __restrict__ Aext, int aggOff,
           const float* __restrict__ W, const float* __restrict__ bias,
           float* __restrict__ Cext, int whOff, int maskBase) {
    __shared__ float As[60 * 132];
    __shared__ float Ws[128 * 16];
    const float* A = (aggOff >= 0) ? (g_agg + aggOff) : Aext;
    float* C = (whOff >= 0) ? (g_Wh + whOff) : Cext;
    int tid = threadIdx.x;
    int c0 = blockIdx.x * 16;

    for (int i = tid; i < 60 * 32; i += 256) {
        int r = i >> 5, q = (i & 31) * 4;
        *(float4*)&As[r * 132 + q] = *(const float4*)&A[r * 128 + q];
    }
    for (int i = tid; i < 512; i += 256) {
        int k = i >> 2, q = (i & 3) * 4;
        *(float4*)&Ws[k * 16 + q] = *(const float4*)&W[k * 128 + c0 + q];
    }
    __syncthreads();

    int row = tid >> 2;
    int jq = (tid & 3) * 4;
    if (row >= 60) return;
    float4 acc = make_float4(0.f, 0.f, 0.f, 0.f);
    #pragma unroll 8
    for (int k = 0; k < 128; k++) {
        float a = As[row * 132 + k];
        float4 w = *(float4*)&Ws[k * 16 + jq];
        acc.x += a * w.x; acc.y += a * w.y; acc.z += a * w.z; acc.w += a * w.w;
    }
    float4 b = *(const float4*)&bias[c0 + jq];
    acc.x += b.x; acc.y += b.y; acc.z += b.z; acc.w += b.w;
    if (maskBase >= 0) {
        int dg = g_off[maskBase + row + 1] - g_off[maskBase + row];
        if (dg == 0) acc = make_float4(0.f, 0.f, 0.f, 0.f);
    }
    *(float4*)&C[row * 128 + c0 + jq] = acc;
}

// ---------------------------------------------------------------------------
// h_paper gather over a PAIR of relations; warp per dst; MLP=4 unroll.
// accum=0: out = sum; accum=1: out += sum.
__global__ void agg_pair(float* __restrict__ out,
                         int offB0, int srtB0, int whB0,
                         int offB1, int srtB1, int whB1, int accum) {
    int w = (blockIdx.x * blockDim.x + threadIdx.x) >> 5;
    if (w >= NP) return;
    int lane = threadIdx.x & 31;
    float4 acc = accum ? *(float4*)&out[w * D + lane * 4]
                       : make_float4(0.f, 0.f, 0.f, 0.f);
    #pragma unroll
    for (int r = 0; r < 2; r++) {
        int offB = r ? offB1 : offB0;
        int srtB = r ? srtB1 : srtB0;
        const float* whb = g_Wh + (r ? whB1 : whB0);
        int s = g_off[offB + w];
        int e = g_off[offB + w + 1];
        int cnt = e - s;
        if (cnt > 0) {
            float4 sum = make_float4(0.f, 0.f, 0.f, 0.f);
            int idx = s;
            for (; idx + 3 < e; idx += 4) {
                int a0 = g_srt[srtB + idx];
                int a1 = g_srt[srtB + idx + 1];
                int a2 = g_srt[srtB + idx + 2];
                int a3 = g_srt[srtB + idx + 3];
                float4 v0 = *(const float4*)&whb[a0 * D + lane * 4];
                float4 v1 = *(const float4*)&whb[a1 * D + lane * 4];
                float4 v2 = *(const float4*)&whb[a2 * D + lane * 4];
                float4 v3 = *(const float4*)&whb[a3 * D + lane * 4];
                sum.x += (v0.x + v1.x) + (v2.x + v3.x);
                sum.y += (v0.y + v1.y) + (v2.y + v3.y);
                sum.z += (v0.z + v1.z) + (v2.z + v3.z);
                sum.w += (v0.w + v1.w) + (v2.w + v3.w);
            }
            for (; idx < e; idx++) {
                int a0 = g_srt[srtB + idx];
                float4 v0 = *(const float4*)&whb[a0 * D + lane * 4];
                sum.x += v0.x; sum.y += v0.y; sum.z += v0.z; sum.w += v0.w;
            }
            float inv = 1.f / (float)cnt;
            acc.x += sum.x * inv; acc.y += sum.y * inv;
            acc.z += sum.z * inv; acc.w += sum.w * inv;
        }
    }
    *(float4*)&out[w * D + lane * 4] = acc;
}

// ---------------------------------------------------------------------------
// mean(x_paper) onto authors (relation wb): warp per author -> g_agg[0..]
__global__ void agg_author(const float* __restrict__ xp) {
    int w = (blockIdx.x * blockDim.x + threadIdx.x) >> 5;
    if (w >= NA) return;
    int lane = threadIdx.x & 31;
    int s = g_off[w];
    int e = g_off[w + 1];
    int cnt = e - s;
    float4 sum = make_float4(0.f, 0.f, 0.f, 0.f);
    int idx = s;
    for (; idx + 3 < e; idx += 4) {
        int a0 = g_srt[idx];
        int a1 = g_srt[idx + 1];
        int a2 = g_srt[idx + 2];
        int a3 = g_srt[idx + 3];
        float4 v0 = *(const float4*)&xp[a0 * D + lane * 4];
        float4 v1 = *(const float4*)&xp[a1 * D + lane * 4];
        float4 v2 = *(const float4*)&xp[a2 * D + lane * 4];
        float4 v3 = *(const float4*)&xp[a3 * D + lane * 4];
        sum.x += (v0.x + v1.x) + (v2.x + v3.x);
        sum.y += (v0.y + v1.y) + (v2.y + v3.y);
        sum.z += (v0.z + v1.z) + (v2.z + v3.z);
        sum.w += (v0.w + v1.w) + (v2.w + v3.w);
    }
    for (; idx < e; idx++) {
        int a0 = g_srt[idx];
        float4 v0 = *(const float4*)&xp[a0 * D + lane * 4];
        sum.x += v0.x; sum.y += v0.y; sum.z += v0.z; sum.w += v0.w;
    }
    float inv = (cnt > 0) ? 1.f / (float)cnt : 0.f;
    float4 o = make_float4(sum.x * inv, sum.y * inv, sum.z * inv, sum.w * inv);
    *(float4*)&g_agg[w * D + lane * 4] = o;
}

// ---------------------------------------------------------------------------
// mean(x_paper) onto subjects (relation ia): one 128-thread block per subject.
__global__ void agg_subject(const float* __restrict__ xp) {
    int dno = blockIdx.x;          // 0..59
    int j = threadIdx.x;           // 0..127
    int s = g_off[180004 + dno];
    int e = g_off[180004 + dno + 1];
    int cnt = e - s;
    float sum = 0.f;
    int idx = s;
    for (; idx + 3 < e; idx += 4) {
        int a = g_srt[1400000 + idx];
        int b = g_srt[1400000 + idx + 1];
        int c = g_srt[1400000 + idx + 2];
        int d = g_srt[1400000 + idx + 3];
        sum += xp[a * D + j] + xp[b * D + j] + xp[c * D + j] + xp[d * D + j];
    }
    for (; idx < e; idx++) sum += xp[g_srt[1400000 + idx] * D + j];
    g_agg[(NA + dno) * D + j] = (cnt > 0) ? sum / (float)cnt : 0.f;
}

// ---------------------------------------------------------------------------
extern "C" void kernel_launch(void* const* d_in, const int* in_sizes, int n_in,
                              void* d_out, int out_size) {
    const float* x_paper   = (const float*)d_in[0];
    const float* x_author  = (const float*)d_in[1];
    const float* x_subject = (const float*)d_in[2];
    const float* W_wb = (const float*)d_in[3];  const float* b_wb = (const float*)d_in[4];
    const float* W_w  = (const float*)d_in[5];  const float* b_w  = (const float*)d_in[6];
    const float* W_c  = (const float*)d_in[7];  const float* b_c  = (const float*)d_in[8];
    const float* W_cd = (const float*)d_in[9];  const float* b_cd = (const float*)d_in[10];
    const float* W_ia = (const float*)d_in[11]; const float* b_ia = (const float*)d_in[12];
    const float* W_h  = (const float*)d_in[13]; const float* b_h  = (const float*)d_in[14];
    const int* src_wb = (const int*)d_in[15];   const int* dst_wb = (const int*)d_in[16];
    const int* src_w  = (const int*)d_in[17];   const int* dst_w  = (const int*)d_in[18];
    const int* src_c  = (const int*)d_in[19];   const int* dst_c  = (const int*)d_in[20];
    const int* src_cd = (const int*)d_in[21];   const int* dst_cd = (const int*)d_in[22];
    const int* src_ia = (const int*)d_in[23];   const int* dst_ia = (const int*)d_in[24];
    const int* src_h  = (const int*)d_in[25];   const int* dst_h  = (const int*)d_in[26];

    float* out         = (float*)d_out;
    float* out_paper   = out;
    float* out_author  = out + NP * D;
    float* out_subject = out + (NP + NA) * D;

    static cudaStream_t s1 = nullptr, s2 = nullptr;
    static cudaEvent_t evA, evCD, evB, evC, evD;
    if (s1 == nullptr) {
        cudaStreamCreateWithFlags(&s1, cudaStreamNonBlocking);
        cudaStreamCreateWithFlags(&s2, cudaStreamNonBlocking);
        cudaEventCreateWithFlags(&evA,  cudaEventDisableTiming);
        cudaEventCreateWithFlags(&evCD, cudaEventDisableTiming);
        cudaEventCreateWithFlags(&evB,  cudaEventDisableTiming);
        cudaEventCreateWithFlags(&evC,  cudaEventDisableTiming);
        cudaEventCreateWithFlags(&evD,  cudaEventDisableTiming);
        cudaFuncSetAttribute(gemm_k, cudaFuncAttributeMaxDynamicSharedMemorySize,
                             GEMM_SMEM);
    }

    // ---- fork ----
    cudaEventRecord(evA, 0);
    cudaStreamWaitEvent(s1, evA, 0);

    // s1: project-first GEMMs; c & cd first so the big gather can start early.
    gemm_k<<<(NP + 127) / 128, 256, GEMM_SMEM, s1>>>(
        x_paper,   -1, W_c,  b_c,  nullptr, NA * D,            NP, -1);
    gemm_k<<<(NP + 127) / 128, 256, GEMM_SMEM, s1>>>(
        x_paper,   -1, W_cd, b_cd, nullptr, (NA + NP) * D,     NP, -1);
    cudaEventRecord(evCD, s1);
    gemm_k<<<(NA + 127) / 128, 256, GEMM_SMEM, s1>>>(
        x_author,  -1, W_w,  b_w,  nullptr, 0,                 NA, -1);
    gemm_small<<<8, 256, 0, s1>>>(
        x_subject, -1, W_h,  b_h,  nullptr, (NA + 2 * NP) * D, -1);
    cudaEventRecord(evB, s1);

    // s0: CSR build + raw-feature aggregations
    zero_kernel<<<(NDST_TOT + 255) / 256, 256>>>();
    count_kernel<<<(375000 + 255) / 256, 256>>>(dst_wb, dst_w, dst_c, dst_cd,
                                                dst_ia, dst_h);
    scan_kernel<<<6, 1024>>>();
    fill_kernel<<<(375000 + 255) / 256, 256>>>(src_wb, dst_wb, src_w, dst_w,
                                               src_c, dst_c, src_cd, dst_cd,
                                               src_ia, dst_ia, src_h, dst_h);
    agg_author<<<(NA * 32 + 255) / 256, 256>>>(x_paper);
    agg_subject<<<NS, 128>>>(x_paper);
    cudaEventRecord(evC, 0);

    // s2: epilogue GEMMs (need g_agg + g_off)
    cudaStreamWaitEvent(s2, evC, 0);
    gemm_k<<<(NA + 127) / 128, 256, GEMM_SMEM, s2>>>(
        nullptr, 0,      W_wb, b_wb, out_author,  -1, NA, 0);
    gemm_small<<<8, 256, 0, s2>>>(
        nullptr, NA * D, W_ia, b_ia, out_subject, -1, 180004);
    cudaEventRecord(evD, s2);

    // s0: paper gathers. c+cd (1M edges) as soon as their GEMMs land;
    // w+h (250k edges) accumulate after the remaining GEMMs.
    cudaStreamWaitEvent(0, evCD, 0);
    agg_pair<<<(NP * 32 + 255) / 256, 256>>>(
        out_paper, 80002, 400000, NA * D,
                   130003, 900000, (NA + NP) * D, 0);
    cudaStreamWaitEvent(0, evB, 0);
    agg_pair<<<(NP * 32 + 255) / 256, 256>>>(
        out_paper, 30001, 200000, 0,
                   180065, 1450000, (NA + 2 * NP) * D, 1);

    // ---- join ----
    cudaStreamWaitEvent(0, evD, 0);
}